// round 10
// baseline (speedup 1.0000x reference)
#include <cuda_runtime.h>
#include <math.h>

#define T_ 16
#define B_ 8
#define H_ 224
#define W_ 224
#define C_ 3
#define CH_ 32
#define OUT_ 10
#define WF_ 113           // W/2 + 1
#define WFP_ 120          // padded to multiple of 8 for vectorized colfft
#define NWG_ 15           // WFP_/8 wf-groups
#define TB_ (T_*B_)

typedef unsigned long long ull;

#define FMA_F32X2(d, a, b) asm("fma.rn.f32x2 %0, %1, %2, %0;" : "+l"(d) : "l"(a), "l"(b))
#define PACK_F32X2(d, lo, hi) asm("mov.b64 %0, {%1, %2};" : "=l"(d) : "f"(lo), "f"(hi))
#define UNPACK_F32X2(lo, hi, d) asm("mov.b64 {%0, %1}, %2;" : "=f"(lo), "=f"(hi) : "l"(d))

// ---------------- device scratch (static: no runtime allocation) ----------------
__device__ float2 g_tw[W_];                          // e^{+i 2pi k/224} table
__device__ float2 g_R[(size_t)TB_*H_*WFP_];          // row rFFT results (padded)
__device__ float  g_mag[(size_t)TB_*H_*WF_];         // log1p|spec|
__device__ float  g_epart[TB_*NWG_];                 // energy partial sums
__device__ int    g_count[T_*B_*CH_];                // spike counts per (t,b,ch)

// ---------------- init: twiddles + zero ALL counters every call ----------------
__global__ void init_kernel() {
    int i = blockIdx.x * blockDim.x + threadIdx.x;
    if (i < W_) {
        double a = (2.0 * 3.141592653589793238462643 * (double)i) / 224.0;
        g_tw[i] = make_float2((float)cos(a), (float)sin(a));
    }
    if (i < T_ * B_ * CH_) g_count[i] = 0;
}

// ---------------- row rFFT: real-fold (half steps) + f32x2 packed complex acc ----------------
__global__ void __launch_bounds__(128) rowfft_kernel(const float* __restrict__ x) {
    __shared__ float  gsh[8][W_];
    __shared__ __align__(8) float2 ab[8][112];
    __shared__ float2 twsh[W_];
    int tid = threadIdx.x;
    int rid0 = blockIdx.x * 8;

    for (int i = tid; i < W_; i += 128) twsh[i] = g_tw[i];
    const float* xb = x + (size_t)rid0 * W_ * 3;
    for (int i = tid; i < 8 * W_; i += 128) {
        float r = xb[i*3+0], g = xb[i*3+1], b = xb[i*3+2];
        ((float*)gsh)[i] = (r + g + b) * (1.0f / 3.0f);
    }
    __syncthreads();

    for (int i = tid; i < 8 * 112; i += 128) {
        int r = i / 112, n = i % 112;
        float a, bv;
        if (n == 0) { a = gsh[r][0]; bv = 0.f; }
        else { float p = gsh[r][n], q = gsh[r][224 - n]; a = p + q; bv = p - q; }
        ab[r][n] = make_float2(a, bv);
    }
    __syncthreads();

    int wf = tid;
    if (wf >= WFP_) return;

    ull acc[8];
    float sg = (wf & 1) ? -1.0f : 1.0f;
    #pragma unroll
    for (int r = 0; r < 8; ++r) {
        float re0 = sg * gsh[r][112];
        PACK_F32X2(acc[r], re0, 0.0f);
    }

    const float cs = twsh[wf].x, ss = twsh[wf].y;
    for (int nb = 0; nb < 112; nb += 16) {
        int idx = (nb * wf) % 224;
        float c = twsh[idx].x, sn = -twsh[idx].y;
        #pragma unroll
        for (int k = 0; k < 16; ++k) {
            ull Wp; PACK_F32X2(Wp, c, sn);
            #pragma unroll
            for (int r = 0; r < 8; ++r) {
                ull abv = *(const ull*)&ab[r][nb + k];
                FMA_F32X2(acc[r], abv, Wp);
            }
            float cn = c * cs + sn * ss;
            sn = sn * cs - c * ss;
            c = cn;
        }
    }
    #pragma unroll
    for (int r = 0; r < 8; ++r) {
        float re, im; UNPACK_F32X2(re, im, acc[r]);
        g_R[(size_t)(rid0 + r) * WFP_ + wf] = make_float2(re, im);
    }
}

// ---------------- column FFT: radix-2 DIT + f32x2 packed, 8 wf-columns per block ----------------
__global__ void __launch_bounds__(224) colfft_kernel() {
    __shared__ __align__(16) char pool[8 * 224 * 16];
    __shared__ float2 twsh[H_];
    __shared__ float  red[7];
    int tid = threadIdx.x;
    int wf0 = blockIdx.x * 8;
    int tb  = blockIdx.y;

    twsh[tid] = g_tw[tid];
    {
        ulonglong2* dup = (ulonglong2*)pool;
        const float4* src = (const float4*)(g_R + ((size_t)tb * H_ + tid) * WFP_ + wf0);
        #pragma unroll
        for (int q = 0; q < 4; ++q) {
            float4 v = src[q];
            ull d0, d1, d2, d3;
            PACK_F32X2(d0, v.x, v.x); PACK_F32X2(d1, v.y, v.y);
            PACK_F32X2(d2, v.z, v.z); PACK_F32X2(d3, v.w, v.w);
            dup[(2*q+0) * 224 + tid] = make_ulonglong2(d0, d1);
            dup[(2*q+1) * 224 + tid] = make_ulonglong2(d2, d3);
        }
    }
    __syncthreads();

    int ro = (tid >= 112) ? 1 : 0;
    int k  = tid - 112 * ro;
    int k2 = 2 * k;

    ull acc[8];
    #pragma unroll
    for (int j = 0; j < 8; ++j) acc[j] = 0ull;

    {
        const ulonglong2* dup = (const ulonglong2*)pool;
        const float cs = twsh[k2].x, ss = twsh[k2].y;
        for (int mb = 0; mb < 112; mb += 16) {
            int idx = (k2 * mb) % 224;
            float c = twsh[idx].x, sn = -twsh[idx].y;
            #pragma unroll
            for (int mm = 0; mm < 16; ++mm) {
                int h = 2 * (mb + mm) + ro;
                ull W1; PACK_F32X2(W1, c, sn);
                float snn = -sn;
                ull W2; PACK_F32X2(W2, snn, c);
                #pragma unroll
                for (int j = 0; j < 8; ++j) {
                    ulonglong2 d = dup[j * 224 + h];
                    FMA_F32X2(acc[j], d.x, W1);
                    FMA_F32X2(acc[j], d.y, W2);
                }
                float cn = c * cs + sn * ss;
                sn = sn * cs - c * ss;
                c = cn;
            }
        }
    }
    __syncthreads();

    ull* Ebuf = (ull*)pool;
    ull* Obuf = (ull*)pool + 8 * 112;
    {
        ull* my = ro ? Obuf : Ebuf;
        #pragma unroll
        for (int j = 0; j < 8; ++j) my[j * 112 + k] = acc[j];
    }
    __syncthreads();

    float sg = ro ? -1.0f : 1.0f;
    float ck = twsh[k].x, sk = twsh[k].y;
    float a1 = sg * ck, a2 = -sg * sk, a3 = sg * sk;
    ull W1p; PACK_F32X2(W1p, a1, a2);
    ull W2p; PACK_F32X2(W2p, a3, a1);

    float esum = 0.f;
    float* mrow = g_mag + ((size_t)tb * H_ + tid) * WF_;
    #pragma unroll
    for (int j = 0; j < 8; ++j) {
        ull X = Ebuf[j * 112 + k];
        ull O = Obuf[j * 112 + k];
        float orr, oii; UNPACK_F32X2(orr, oii, O);
        ull P1; PACK_F32X2(P1, orr, orr);
        ull P2; PACK_F32X2(P2, oii, oii);
        FMA_F32X2(X, P1, W1p);
        FMA_F32X2(X, P2, W2p);
        float re, im; UNPACK_F32X2(re, im, X);
        int wf = wf0 + j;
        if (wf < WF_) {
            float m = log1pf(sqrtf(re * re + im * im));
            mrow[wf] = m;
            esum += m;
        }
    }
    #pragma unroll
    for (int o = 16; o; o >>= 1) esum += __shfl_down_sync(0xffffffffu, esum, o);
    if ((tid & 31) == 0) red[tid >> 5] = esum;
    __syncthreads();
    if (tid == 0) {
        float tot = 0.f;
        #pragma unroll
        for (int i = 0; i < 7; ++i) tot += red[i];
        g_epart[tb * NWG_ + blockIdx.x] = tot;
    }
}

// ---------------- fused conv3x3(4->32) + LIF: 8x16 tile, 4 px/thread, high occupancy ------
// Warp w owns channels 4w..4w+3. Lane l: row = l&15, half = l>>4 (4-px halves).
// Plane stride 12 floats -> group stride 3 (odd) -> conflict-free LDS.128.
// Per-t spike counts: 1 packed STS per thread; block-wide reduce once at end (no shuffles).
#define TLW_ 12            // padded plane row stride (10 used)
#define PLS_ (18 * TLW_)   // 216 floats per plane

__device__ __forceinline__ void fill_tile(float* __restrict__ pls,
                                          const float* __restrict__ x,
                                          int t, int b, int by0, int bx0, int tid) {
    const float sc = (float)WF_ / (float)W_;
    for (int i = tid; i < 18 * 10; i += 256) {
        int ly = i / 10, lx = i % 10;
        int gy = by0 + ly - 1, gx = bx0 + lx - 1;
        float vr = 0.f, vg = 0.f, vb = 0.f, vm = 0.f;
        if (gy >= 0 && gy < H_ && gx >= 0 && gx < W_) {
            size_t base = (((size_t)t * B_ + b) * H_ + gy) * W_ + gx;
            const float* px = x + base * 3;
            vr = px[0]; vg = px[1]; vb = px[2];
            float u  = (gx + 0.5f) * sc - 0.5f;
            float fj = floorf(u);
            float f  = u - fj;
            int j = (int)fj;
            int i0 = j < 0 ? 0 : (j > WF_-1 ? WF_-1 : j);
            int i1 = j+1 < 0 ? 0 : (j+1 > WF_-1 ? WF_-1 : j+1);
            const float* mrow = g_mag + (((size_t)t * B_ + b) * H_ + gy) * WF_;
            vm = (1.0f - f) * mrow[i0] + f * mrow[i1];
        }
        int o = ly * TLW_ + lx;
        pls[0*PLS_ + o] = vr;
        pls[1*PLS_ + o] = vg;
        pls[2*PLS_ + o] = vb;
        pls[3*PLS_ + o] = vm;
    }
}

__global__ void __launch_bounds__(256, 3) convlif_kernel(const float* __restrict__ x,
                                                         const float* __restrict__ cw,
                                                         const float* __restrict__ cb) {
    __shared__ __align__(16) float planes[2][4 * PLS_];
    __shared__ __align__(16) ulonglong2 wq[9][4][8];   // [p][ic][warpgroup] = {pair01, pair23}
    __shared__ float bsh[CH_];
    __shared__ int cnt_raw[T_][256];                   // packed per-thread counts (all written each t)

    int tid = threadIdx.x;
    int w = tid >> 5;          // warp = channel group (4 channels 4w..4w+3)
    int l = tid & 31;
    int r = l & 15;            // output row within 16-tall tile
    int hx = l >> 4;           // 4-px half
    int c0 = hx * 4;           // first output col within 8-wide tile
    int b = blockIdx.z;
    int by0 = blockIdx.y * 16, bx0 = blockIdx.x * 8;

    for (int i = tid; i < 9 * 4 * 8; i += 256) {
        int pi = i >> 3, wg = i & 7;
        const float* src = cw + pi * CH_ + 4 * wg;
        ull q0, q1;
        PACK_F32X2(q0, src[0], src[1]);
        PACK_F32X2(q1, src[2], src[3]);
        ((ulonglong2*)wq)[i] = make_ulonglong2(q0, q1);
    }
    if (tid < CH_) bsh[tid] = cb[tid];

    fill_tile(&planes[0][0], x, 0, b, by0, bx0, tid);
    __syncthreads();

    ull bias2[2];
    { float b0 = bsh[4*w+0], b1 = bsh[4*w+1], b2 = bsh[4*w+2], b3 = bsh[4*w+3];
      PACK_F32X2(bias2[0], b0, b1);
      PACK_F32X2(bias2[1], b2, b3); }

    ull K09;
    { float k = 0.9f; PACK_F32X2(K09, k, k); }

    ull V2[2][4];
    #pragma unroll
    for (int c = 0; c < 2; ++c)
        #pragma unroll
        for (int j = 0; j < 4; ++j) V2[c][j] = 0ull;

    #pragma unroll 1
    for (int t = 0; t < T_; ++t) {
        int bb = t & 1;
        if (t + 1 < T_) fill_tile(&planes[bb ^ 1][0], x, t + 1, b, by0, bx0, tid);

        ull acc[2][4];
        #pragma unroll
        for (int c = 0; c < 2; ++c)
            #pragma unroll
            for (int j = 0; j < 4; ++j) acc[c][j] = bias2[c];

        #pragma unroll
        for (int ky = 0; ky < 3; ++ky) {
            #pragma unroll
            for (int ic = 0; ic < 4; ++ic) {
                const float* pl = &planes[bb][ic * PLS_ + (r + ky) * TLW_ + c0];
                float4 a0 = *(const float4*)(pl + 0);
                float2 a1 = *(const float2*)(pl + 4);
                ull A[6];
                PACK_F32X2(A[0], a0.x, a0.x);
                PACK_F32X2(A[1], a0.y, a0.y);
                PACK_F32X2(A[2], a0.z, a0.z);
                PACK_F32X2(A[3], a0.w, a0.w);
                PACK_F32X2(A[4], a1.x, a1.x);
                PACK_F32X2(A[5], a1.y, a1.y);
                #pragma unroll
                for (int kx = 0; kx < 3; ++kx) {
                    int p = ky * 3 + kx;
                    ulonglong2 q = wq[p][ic][w];   // broadcast LDS.128 (1 wavefront)
                    #pragma unroll
                    for (int j = 0; j < 4; ++j) {
                        FMA_F32X2(acc[0][j], A[j + kx], q.x);
                        FMA_F32X2(acc[1][j], A[j + kx], q.y);
                    }
                }
            }
        }

        int n[4] = {0, 0, 0, 0};
        #pragma unroll
        for (int c = 0; c < 2; ++c) {
            #pragma unroll
            for (int j = 0; j < 4; ++j) {
                FMA_F32X2(acc[c][j], V2[c][j], K09);
                float lo, hi;
                UNPACK_F32X2(lo, hi, acc[c][j]);
                if (lo > 1.0f) { lo -= 1.0f; n[2*c+0]++; }
                if (hi > 1.0f) { hi -= 1.0f; n[2*c+1]++; }
                PACK_F32X2(V2[c][j], lo, hi);
            }
        }
        cnt_raw[t][tid] = n[0] | (n[1] << 8) | (n[2] << 16) | (n[3] << 24);
        __syncthreads();
    }

    // block-wide count reduction (once): (t,ch) <- sum of byte c over warp wgrp's 32 lanes
    for (int i = tid; i < T_ * CH_; i += 256) {
        int t = i >> 5, ch = i & 31;
        int wgrp = ch >> 2, c = ch & 3;
        const int* row = &cnt_raw[t][wgrp * 32];
        int s = 0;
        #pragma unroll
        for (int lane = 0; lane < 32; ++lane) s += (row[lane] >> (8 * c)) & 0xff;
        atomicAdd(&g_count[(t * B_ + b) * CH_ + ch], s);
    }
}

// ---------------- finalize: logits, readout, spike rate, energy ----------------
__global__ void __launch_bounds__(256) finalize_kernel(const float* __restrict__ hw_g,
                                                       const float* __restrict__ hb_g,
                                                       float* __restrict__ out, int out_size) {
    __shared__ float hw[CH_ * OUT_];
    __shared__ float hb[OUT_];
    __shared__ float logits[T_ * B_ * OUT_];
    __shared__ float red[256];
    int tid = threadIdx.x;
    for (int i = tid; i < CH_ * OUT_; i += 256) hw[i] = hw_g[i];
    if (tid < OUT_) hb[tid] = hb_g[tid];
    __syncthreads();

    const float inv = 1.0f / ((float)(H_ * W_));
    for (int i = tid; i < T_ * B_ * OUT_; i += 256) {
        int o = i % OUT_;
        int tb = i / OUT_;
        float a = hb[o];
        const int* c = &g_count[tb * CH_];
        #pragma unroll
        for (int ch = 0; ch < CH_; ++ch)
            a += ((float)c[ch] * inv) * hw[ch * OUT_ + o];
        logits[i] = a;
    }
    __syncthreads();

    if (out_size >= B_*OUT_ + T_*B_*OUT_ + 2) {
        for (int i = tid; i < T_ * B_ * OUT_; i += 256)
            out[B_ * OUT_ + i] = logits[i];
    }
    if (tid < B_ * OUT_) {
        float s = 0.f;
        for (int t = 0; t < T_; ++t) s += logits[t * B_ * OUT_ + tid];
        out[tid] = s * (1.0f / (float)T_);
    }

    {   // spike rate
        float s = 0.f;
        for (int i = tid; i < T_ * B_ * CH_; i += 256) s += (float)g_count[i];
        red[tid] = s;
        __syncthreads();
        for (int st = 128; st; st >>= 1) { if (tid < st) red[tid] += red[tid + st]; __syncthreads(); }
        if (tid == 0 && out_size >= B_*OUT_ + T_*B_*OUT_ + 1)
            out[B_*OUT_ + T_*B_*OUT_] = red[0] / ((float)T_ * B_ * CH_ * H_ * W_);
        __syncthreads();
    }
    {   // spectral energy
        float s = 0.f;
        for (int i = tid; i < TB_ * NWG_; i += 256) s += g_epart[i];
        red[tid] = s;
        __syncthreads();
        for (int st = 128; st; st >>= 1) { if (tid < st) red[tid] += red[tid + st]; __syncthreads(); }
        if (tid == 0 && out_size >= B_*OUT_ + T_*B_*OUT_ + 2)
            out[B_*OUT_ + T_*B_*OUT_ + 1] = red[0] / ((float)T_ * B_ * H_ * WF_);
    }
}

// ---------------- launch ----------------
extern "C" void kernel_launch(void* const* d_in, const int* in_sizes, int n_in,
                              void* d_out, int out_size) {
    const float* x_seq  = (const float*)d_in[0];
    const float* conv_w = (const float*)d_in[1];
    const float* conv_b = (const float*)d_in[2];
    const float* head_w = (const float*)d_in[3];
    const float* head_b = (const float*)d_in[4];
    float* out = (float*)d_out;

    init_kernel<<<16, 256>>>();
    rowfft_kernel<<<TB_ * H_ / 8, 128>>>(x_seq);
    colfft_kernel<<<dim3(NWG_, TB_), 224>>>();
    convlif_kernel<<<dim3(W_/8, H_/16, B_), 256>>>(x_seq, conv_w, conv_b);
    finalize_kernel<<<1, 256>>>(head_w, head_b, out, out_size);
}

// round 11
// speedup vs baseline: 1.0032x; 1.0032x over previous
#include <cuda_runtime.h>
#include <math.h>

#define T_ 16
#define B_ 8
#define H_ 224
#define W_ 224
#define C_ 3
#define CH_ 32
#define OUT_ 10
#define WF_ 113           // W/2 + 1
#define WFP_ 120          // padded to multiple of 8 for vectorized colfft
#define NWG_ 15           // WFP_/8 wf-groups
#define TB_ (T_*B_)

typedef unsigned long long ull;

#define FMA_F32X2(d, a, b) asm("fma.rn.f32x2 %0, %1, %2, %0;" : "+l"(d) : "l"(a), "l"(b))
#define PACK_F32X2(d, lo, hi) asm("mov.b64 %0, {%1, %2};" : "=l"(d) : "f"(lo), "f"(hi))
#define UNPACK_F32X2(lo, hi, d) asm("mov.b64 {%0, %1}, %2;" : "=f"(lo), "=f"(hi) : "l"(d))

// ---------------- device scratch (static: no runtime allocation) ----------------
__device__ float2 g_tw[W_];                          // e^{+i 2pi k/224} table
__device__ float2 g_R[(size_t)TB_*H_*WFP_];          // row rFFT results (padded)
__device__ float  g_mag[(size_t)TB_*H_*WF_];         // log1p|spec|
__device__ float  g_epart[TB_*NWG_];                 // energy partial sums
__device__ int    g_count[T_*B_*CH_];                // spike counts per (t,b,ch)

// ---------------- init: twiddles + zero ALL counters every call ----------------
__global__ void init_kernel() {
    int i = blockIdx.x * blockDim.x + threadIdx.x;
    if (i < W_) {
        double a = (2.0 * 3.141592653589793238462643 * (double)i) / 224.0;
        g_tw[i] = make_float2((float)cos(a), (float)sin(a));
    }
    if (i < T_ * B_ * CH_) g_count[i] = 0;
}

// ---------------- row rFFT: real-fold (half steps) + f32x2 packed complex acc ----------------
__global__ void __launch_bounds__(128) rowfft_kernel(const float* __restrict__ x) {
    __shared__ float  gsh[8][W_];
    __shared__ __align__(8) float2 ab[8][112];
    __shared__ float2 twsh[W_];
    int tid = threadIdx.x;
    int rid0 = blockIdx.x * 8;

    for (int i = tid; i < W_; i += 128) twsh[i] = g_tw[i];
    const float* xb = x + (size_t)rid0 * W_ * 3;
    for (int i = tid; i < 8 * W_; i += 128) {
        float r = xb[i*3+0], g = xb[i*3+1], b = xb[i*3+2];
        ((float*)gsh)[i] = (r + g + b) * (1.0f / 3.0f);
    }
    __syncthreads();

    for (int i = tid; i < 8 * 112; i += 128) {
        int r = i / 112, n = i % 112;
        float a, bv;
        if (n == 0) { a = gsh[r][0]; bv = 0.f; }
        else { float p = gsh[r][n], q = gsh[r][224 - n]; a = p + q; bv = p - q; }
        ab[r][n] = make_float2(a, bv);
    }
    __syncthreads();

    int wf = tid;
    if (wf >= WFP_) return;

    ull acc[8];
    float sg = (wf & 1) ? -1.0f : 1.0f;
    #pragma unroll
    for (int r = 0; r < 8; ++r) {
        float re0 = sg * gsh[r][112];
        PACK_F32X2(acc[r], re0, 0.0f);
    }

    const float cs = twsh[wf].x, ss = twsh[wf].y;
    for (int nb = 0; nb < 112; nb += 16) {
        int idx = (nb * wf) % 224;
        float c = twsh[idx].x, sn = -twsh[idx].y;
        #pragma unroll
        for (int k = 0; k < 16; ++k) {
            ull Wp; PACK_F32X2(Wp, c, sn);
            #pragma unroll
            for (int r = 0; r < 8; ++r) {
                ull abv = *(const ull*)&ab[r][nb + k];
                FMA_F32X2(acc[r], abv, Wp);
            }
            float cn = c * cs + sn * ss;
            sn = sn * cs - c * ss;
            c = cn;
        }
    }
    #pragma unroll
    for (int r = 0; r < 8; ++r) {
        float re, im; UNPACK_F32X2(re, im, acc[r]);
        g_R[(size_t)(rid0 + r) * WFP_ + wf] = make_float2(re, im);
    }
}

// ---------------- column FFT: radix-2 DIT + f32x2 packed, 8 wf-columns per block ----------------
__global__ void __launch_bounds__(224) colfft_kernel() {
    __shared__ __align__(16) char pool[8 * 224 * 16];
    __shared__ float2 twsh[H_];
    __shared__ float  red[7];
    int tid = threadIdx.x;
    int wf0 = blockIdx.x * 8;
    int tb  = blockIdx.y;

    twsh[tid] = g_tw[tid];
    {
        ulonglong2* dup = (ulonglong2*)pool;
        const float4* src = (const float4*)(g_R + ((size_t)tb * H_ + tid) * WFP_ + wf0);
        #pragma unroll
        for (int q = 0; q < 4; ++q) {
            float4 v = src[q];
            ull d0, d1, d2, d3;
            PACK_F32X2(d0, v.x, v.x); PACK_F32X2(d1, v.y, v.y);
            PACK_F32X2(d2, v.z, v.z); PACK_F32X2(d3, v.w, v.w);
            dup[(2*q+0) * 224 + tid] = make_ulonglong2(d0, d1);
            dup[(2*q+1) * 224 + tid] = make_ulonglong2(d2, d3);
        }
    }
    __syncthreads();

    int ro = (tid >= 112) ? 1 : 0;
    int k  = tid - 112 * ro;
    int k2 = 2 * k;

    ull acc[8];
    #pragma unroll
    for (int j = 0; j < 8; ++j) acc[j] = 0ull;

    {
        const ulonglong2* dup = (const ulonglong2*)pool;
        const float cs = twsh[k2].x, ss = twsh[k2].y;
        for (int mb = 0; mb < 112; mb += 16) {
            int idx = (k2 * mb) % 224;
            float c = twsh[idx].x, sn = -twsh[idx].y;
            #pragma unroll
            for (int mm = 0; mm < 16; ++mm) {
                int h = 2 * (mb + mm) + ro;
                ull W1; PACK_F32X2(W1, c, sn);
                float snn = -sn;
                ull W2; PACK_F32X2(W2, snn, c);
                #pragma unroll
                for (int j = 0; j < 8; ++j) {
                    ulonglong2 d = dup[j * 224 + h];
                    FMA_F32X2(acc[j], d.x, W1);
                    FMA_F32X2(acc[j], d.y, W2);
                }
                float cn = c * cs + sn * ss;
                sn = sn * cs - c * ss;
                c = cn;
            }
        }
    }
    __syncthreads();

    ull* Ebuf = (ull*)pool;
    ull* Obuf = (ull*)pool + 8 * 112;
    {
        ull* my = ro ? Obuf : Ebuf;
        #pragma unroll
        for (int j = 0; j < 8; ++j) my[j * 112 + k] = acc[j];
    }
    __syncthreads();

    float sg = ro ? -1.0f : 1.0f;
    float ck = twsh[k].x, sk = twsh[k].y;
    float a1 = sg * ck, a2 = -sg * sk, a3 = sg * sk;
    ull W1p; PACK_F32X2(W1p, a1, a2);
    ull W2p; PACK_F32X2(W2p, a3, a1);

    float esum = 0.f;
    float* mrow = g_mag + ((size_t)tb * H_ + tid) * WF_;
    #pragma unroll
    for (int j = 0; j < 8; ++j) {
        ull X = Ebuf[j * 112 + k];
        ull O = Obuf[j * 112 + k];
        float orr, oii; UNPACK_F32X2(orr, oii, O);
        ull P1; PACK_F32X2(P1, orr, orr);
        ull P2; PACK_F32X2(P2, oii, oii);
        FMA_F32X2(X, P1, W1p);
        FMA_F32X2(X, P2, W2p);
        float re, im; UNPACK_F32X2(re, im, X);
        int wf = wf0 + j;
        if (wf < WF_) {
            float m = log1pf(sqrtf(re * re + im * im));
            mrow[wf] = m;
            esum += m;
        }
    }
    #pragma unroll
    for (int o = 16; o; o >>= 1) esum += __shfl_down_sync(0xffffffffu, esum, o);
    if ((tid & 31) == 0) red[tid >> 5] = esum;
    __syncthreads();
    if (tid == 0) {
        float tot = 0.f;
        #pragma unroll
        for (int i = 0; i < 7; ++i) tot += red[i];
        g_epart[tb * NWG_ + blockIdx.x] = tot;
    }
}

// ---------------- fused conv3x3(4->32) + LIF: 8x16 tile, 4 px/thread, high occupancy ------
// Warp w owns channels 4w..4w+3. Lane l: row = l&15, half = l>>4 (4-px halves).
// Plane stride 12 floats -> group stride 3 (odd) -> conflict-free LDS.128.
// Per-t spike counts: 1 packed STS per thread; block-wide reduce once at end (no shuffles).
#define TLW_ 12            // padded plane row stride (10 used)
#define PLS_ (18 * TLW_)   // 216 floats per plane

__device__ __forceinline__ void fill_tile(float* __restrict__ pls,
                                          const float* __restrict__ x,
                                          int t, int b, int by0, int bx0, int tid) {
    const float sc = (float)WF_ / (float)W_;
    for (int i = tid; i < 18 * 10; i += 256) {
        int ly = i / 10, lx = i % 10;
        int gy = by0 + ly - 1, gx = bx0 + lx - 1;
        float vr = 0.f, vg = 0.f, vb = 0.f, vm = 0.f;
        if (gy >= 0 && gy < H_ && gx >= 0 && gx < W_) {
            size_t base = (((size_t)t * B_ + b) * H_ + gy) * W_ + gx;
            const float* px = x + base * 3;
            vr = px[0]; vg = px[1]; vb = px[2];
            float u  = (gx + 0.5f) * sc - 0.5f;
            float fj = floorf(u);
            float f  = u - fj;
            int j = (int)fj;
            int i0 = j < 0 ? 0 : (j > WF_-1 ? WF_-1 : j);
            int i1 = j+1 < 0 ? 0 : (j+1 > WF_-1 ? WF_-1 : j+1);
            const float* mrow = g_mag + (((size_t)t * B_ + b) * H_ + gy) * WF_;
            vm = (1.0f - f) * mrow[i0] + f * mrow[i1];
        }
        int o = ly * TLW_ + lx;
        pls[0*PLS_ + o] = vr;
        pls[1*PLS_ + o] = vg;
        pls[2*PLS_ + o] = vb;
        pls[3*PLS_ + o] = vm;
    }
}

__global__ void __launch_bounds__(256, 3) convlif_kernel(const float* __restrict__ x,
                                                         const float* __restrict__ cw,
                                                         const float* __restrict__ cb) {
    __shared__ __align__(16) float planes[2][4 * PLS_];
    __shared__ __align__(16) ulonglong2 wq[9][4][8];   // [p][ic][warpgroup] = {pair01, pair23}
    __shared__ float bsh[CH_];
    __shared__ int cnt_raw[T_][256];                   // packed per-thread counts (all written each t)

    int tid = threadIdx.x;
    int w = tid >> 5;          // warp = channel group (4 channels 4w..4w+3)
    int l = tid & 31;
    int r = l & 15;            // output row within 16-tall tile
    int hx = l >> 4;           // 4-px half
    int c0 = hx * 4;           // first output col within 8-wide tile
    int b = blockIdx.z;
    int by0 = blockIdx.y * 16, bx0 = blockIdx.x * 8;

    for (int i = tid; i < 9 * 4 * 8; i += 256) {
        int pi = i >> 3, wg = i & 7;
        const float* src = cw + pi * CH_ + 4 * wg;
        ull q0, q1;
        PACK_F32X2(q0, src[0], src[1]);
        PACK_F32X2(q1, src[2], src[3]);
        ((ulonglong2*)wq)[i] = make_ulonglong2(q0, q1);
    }
    if (tid < CH_) bsh[tid] = cb[tid];

    fill_tile(&planes[0][0], x, 0, b, by0, bx0, tid);
    __syncthreads();

    ull bias2[2];
    { float b0 = bsh[4*w+0], b1 = bsh[4*w+1], b2 = bsh[4*w+2], b3 = bsh[4*w+3];
      PACK_F32X2(bias2[0], b0, b1);
      PACK_F32X2(bias2[1], b2, b3); }

    ull K09;
    { float k = 0.9f; PACK_F32X2(K09, k, k); }

    ull V2[2][4];
    #pragma unroll
    for (int c = 0; c < 2; ++c)
        #pragma unroll
        for (int j = 0; j < 4; ++j) V2[c][j] = 0ull;

    #pragma unroll 1
    for (int t = 0; t < T_; ++t) {
        int bb = t & 1;
        if (t + 1 < T_) fill_tile(&planes[bb ^ 1][0], x, t + 1, b, by0, bx0, tid);

        ull acc[2][4];
        #pragma unroll
        for (int c = 0; c < 2; ++c)
            #pragma unroll
            for (int j = 0; j < 4; ++j) acc[c][j] = bias2[c];

        #pragma unroll
        for (int ky = 0; ky < 3; ++ky) {
            #pragma unroll
            for (int ic = 0; ic < 4; ++ic) {
                const float* pl = &planes[bb][ic * PLS_ + (r + ky) * TLW_ + c0];
                float4 a0 = *(const float4*)(pl + 0);
                float2 a1 = *(const float2*)(pl + 4);
                ull A[6];
                PACK_F32X2(A[0], a0.x, a0.x);
                PACK_F32X2(A[1], a0.y, a0.y);
                PACK_F32X2(A[2], a0.z, a0.z);
                PACK_F32X2(A[3], a0.w, a0.w);
                PACK_F32X2(A[4], a1.x, a1.x);
                PACK_F32X2(A[5], a1.y, a1.y);
                #pragma unroll
                for (int kx = 0; kx < 3; ++kx) {
                    int p = ky * 3 + kx;
                    ulonglong2 q = wq[p][ic][w];   // broadcast LDS.128 (1 wavefront)
                    #pragma unroll
                    for (int j = 0; j < 4; ++j) {
                        FMA_F32X2(acc[0][j], A[j + kx], q.x);
                        FMA_F32X2(acc[1][j], A[j + kx], q.y);
                    }
                }
            }
        }

        int n[4] = {0, 0, 0, 0};
        #pragma unroll
        for (int c = 0; c < 2; ++c) {
            #pragma unroll
            for (int j = 0; j < 4; ++j) {
                FMA_F32X2(acc[c][j], V2[c][j], K09);
                float lo, hi;
                UNPACK_F32X2(lo, hi, acc[c][j]);
                if (lo > 1.0f) { lo -= 1.0f; n[2*c+0]++; }
                if (hi > 1.0f) { hi -= 1.0f; n[2*c+1]++; }
                PACK_F32X2(V2[c][j], lo, hi);
            }
        }
        cnt_raw[t][tid] = n[0] | (n[1] << 8) | (n[2] << 16) | (n[3] << 24);
        __syncthreads();
    }

    // block-wide count reduction (once): (t,ch) <- sum of byte c over warp wgrp's 32 lanes
    for (int i = tid; i < T_ * CH_; i += 256) {
        int t = i >> 5, ch = i & 31;
        int wgrp = ch >> 2, c = ch & 3;
        const int* row = &cnt_raw[t][wgrp * 32];
        int s = 0;
        #pragma unroll
        for (int lane = 0; lane < 32; ++lane) s += (row[lane] >> (8 * c)) & 0xff;
        atomicAdd(&g_count[(t * B_ + b) * CH_ + ch], s);
    }
}

// ---------------- finalize: logits, readout, spike rate, energy ----------------
__global__ void __launch_bounds__(256) finalize_kernel(const float* __restrict__ hw_g,
                                                       const float* __restrict__ hb_g,
                                                       float* __restrict__ out, int out_size) {
    __shared__ float hw[CH_ * OUT_];
    __shared__ float hb[OUT_];
    __shared__ float logits[T_ * B_ * OUT_];
    __shared__ float red[256];
    int tid = threadIdx.x;
    for (int i = tid; i < CH_ * OUT_; i += 256) hw[i] = hw_g[i];
    if (tid < OUT_) hb[tid] = hb_g[tid];
    __syncthreads();

    const float inv = 1.0f / ((float)(H_ * W_));
    for (int i = tid; i < T_ * B_ * OUT_; i += 256) {
        int o = i % OUT_;
        int tb = i / OUT_;
        float a = hb[o];
        const int* c = &g_count[tb * CH_];
        #pragma unroll
        for (int ch = 0; ch < CH_; ++ch)
            a += ((float)c[ch] * inv) * hw[ch * OUT_ + o];
        logits[i] = a;
    }
    __syncthreads();

    if (out_size >= B_*OUT_ + T_*B_*OUT_ + 2) {
        for (int i = tid; i < T_ * B_ * OUT_; i += 256)
            out[B_ * OUT_ + i] = logits[i];
    }
    if (tid < B_ * OUT_) {
        float s = 0.f;
        for (int t = 0; t < T_; ++t) s += logits[t * B_ * OUT_ + tid];
        out[tid] = s * (1.0f / (float)T_);
    }

    {   // spike rate
        float s = 0.f;
        for (int i = tid; i < T_ * B_ * CH_; i += 256) s += (float)g_count[i];
        red[tid] = s;
        __syncthreads();
        for (int st = 128; st; st >>= 1) { if (tid < st) red[tid] += red[tid + st]; __syncthreads(); }
        if (tid == 0 && out_size >= B_*OUT_ + T_*B_*OUT_ + 1)
            out[B_*OUT_ + T_*B_*OUT_] = red[0] / ((float)T_ * B_ * CH_ * H_ * W_);
        __syncthreads();
    }
    {   // spectral energy
        float s = 0.f;
        for (int i = tid; i < TB_ * NWG_; i += 256) s += g_epart[i];
        red[tid] = s;
        __syncthreads();
        for (int st = 128; st; st >>= 1) { if (tid < st) red[tid] += red[tid + st]; __syncthreads(); }
        if (tid == 0 && out_size >= B_*OUT_ + T_*B_*OUT_ + 2)
            out[B_*OUT_ + T_*B_*OUT_ + 1] = red[0] / ((float)T_ * B_ * H_ * WF_);
    }
}

// ---------------- launch ----------------
extern "C" void kernel_launch(void* const* d_in, const int* in_sizes, int n_in,
                              void* d_out, int out_size) {
    const float* x_seq  = (const float*)d_in[0];
    const float* conv_w = (const float*)d_in[1];
    const float* conv_b = (const float*)d_in[2];
    const float* head_w = (const float*)d_in[3];
    const float* head_b = (const float*)d_in[4];
    float* out = (float*)d_out;

    init_kernel<<<16, 256>>>();
    rowfft_kernel<<<TB_ * H_ / 8, 128>>>(x_seq);
    colfft_kernel<<<dim3(NWG_, TB_), 224>>>();
    convlif_kernel<<<dim3(W_/8, H_/16, B_), 256>>>(x_seq, conv_w, conv_b);
    finalize_kernel<<<1, 256>>>(head_w, head_b, out, out_size);
}